// round 14
// baseline (speedup 1.0000x reference)
#include <cuda_runtime.h>
#include <cuda_bf16.h>
#include <cstdint>

// FactoredQuantizer: B=8192, M=16, N=256, C=64
// R13: mma.sync bf16 3-term split (mapping verified rel_err=0 in R10/R11).
// Serial predicated argmin epilogue replaced by branchless u64-key top-2
// tournament; cross-term accumulators split for ILP; 2 CTAs/SM.

#define BQ 8192
#define MQ 16
#define NQ 256
#define CQ 64
#define QT 128
#define NTHREADS 256
#define TAU 0.015625f
#define FLT_BIG 3.402823466e38f

#define SW128(bo) ((bo) ^ (((bo) >> 3) & 0x70))

// smem layout (bf16 rows = 128 B, SW128 swizzle)
#define SM_A_HI 0            // [128][64] bf16 = 16 KB
#define SM_A_LO 16384
#define SM_B_HI 32768        // [256][64] bf16 = 32 KB
#define SM_B_LO 65536
#define SM_C2   98304        // 256 f32
#define SM_WIN  99328        // 128 int
#define SM_TOTAL 99840

typedef unsigned long long u64;

__device__ __forceinline__ uint32_t smem_u32(const void* p) {
    uint32_t a;
    asm("{ .reg .u64 t; cvta.to.shared.u64 t, %1; cvt.u32.u64 %0, t; }"
        : "=r"(a) : "l"(p));
    return a;
}
__device__ __forceinline__ void ldmx4(uint32_t* r, uint32_t addr) {
    asm volatile("ldmatrix.sync.aligned.m8n8.x4.shared.b16 {%0,%1,%2,%3}, [%4];"
                 : "=r"(r[0]), "=r"(r[1]), "=r"(r[2]), "=r"(r[3]) : "r"(addr));
}
__device__ __forceinline__ void mma_bf16(float* c, const uint32_t* a,
                                         uint32_t b0, uint32_t b1) {
    asm volatile(
        "mma.sync.aligned.m16n8k16.row.col.f32.bf16.bf16.f32 "
        "{%0,%1,%2,%3}, {%4,%5,%6,%7}, {%8,%9}, {%0,%1,%2,%3};"
        : "+f"(c[0]), "+f"(c[1]), "+f"(c[2]), "+f"(c[3])
        : "r"(a[0]), "r"(a[1]), "r"(a[2]), "r"(a[3]), "r"(b0), "r"(b1));
}

// monotone float -> ordered u32 (ascending), incl. negatives
__device__ __forceinline__ uint32_t ford(float f) {
    uint32_t u = __float_as_uint(f);
    return u ^ ((uint32_t)((int)u >> 31) | 0x80000000u);
}
__device__ __forceinline__ float iord(uint32_t o) {
    uint32_t u = (o & 0x80000000u) ? (o ^ 0x80000000u) : ~o;
    return __uint_as_float(u);
}
__device__ __forceinline__ u64 umin64(u64 a, u64 b) { return a < b ? a : b; }
__device__ __forceinline__ u64 umax64(u64 a, u64 b) { return a < b ? b : a; }

__device__ __forceinline__ void cvt_store_pair(char* hi_base, char* lo_base,
                                               uint32_t bo, float a, float b) {
    __nv_bfloat16 ha = __float2bfloat16(a), hb = __float2bfloat16(b);
    float la = a - __bfloat162float(ha);
    float lb = b - __bfloat162float(hb);
    __nv_bfloat16 lha = __float2bfloat16(la), lhb = __float2bfloat16(lb);
    uint32_t hw = (uint32_t)__bfloat16_as_ushort(ha)
                | ((uint32_t)__bfloat16_as_ushort(hb) << 16);
    uint32_t lw = (uint32_t)__bfloat16_as_ushort(lha)
                | ((uint32_t)__bfloat16_as_ushort(lhb) << 16);
    uint32_t so = SW128(bo);
    *(uint32_t*)(hi_base + so) = hw;
    *(uint32_t*)(lo_base + so) = lw;
}

__device__ __forceinline__ float exact_dist(const float* __restrict__ xr,
                                            const float* __restrict__ cr,
                                            float c2n) {
    float s = 0.f;
    #pragma unroll 8
    for (int k = 0; k < CQ; k++) s = fmaf(xr[k], cr[k], s);
    return fmaf(-2.0f, s, c2n);
}

__global__ __launch_bounds__(NTHREADS, 2)
void fq_mma_kernel(const float* __restrict__ x,
                   const float* __restrict__ cb,
                   float* __restrict__ out_codes,
                   float* __restrict__ out_idx) {
    extern __shared__ char smem[];
    const uint32_t sb = smem_u32(smem);
    float* s_c2  = (float*)(smem + SM_C2);
    int*   s_win = (int*)  (smem + SM_WIN);

    const int t = threadIdx.x, wid = t >> 5, lane = t & 31;
    const int m = blockIdx.y;
    const int qbase = blockIdx.x * QT;
    const float* gcb = cb + (size_t)m * NQ * CQ;

    // ---- stage A = x tile [128][64]: f32 -> bf16 hi/lo, SW128 ----
    #pragma unroll
    for (int i = 0; i < 8; i++) {
        int idx = t + NTHREADS * i;
        int row = idx >> 4, c4 = idx & 15;
        float4 v = *(const float4*)(x + ((size_t)(qbase + row) * MQ + m) * CQ + c4 * 4);
        uint32_t bo = row * 128 + c4 * 8;
        cvt_store_pair(smem + SM_A_HI, smem + SM_A_LO, bo,     v.x, v.y);
        cvt_store_pair(smem + SM_A_HI, smem + SM_A_LO, bo + 4, v.z, v.w);
    }
    // ---- stage B = codebook[m] [256][64] ----
    #pragma unroll
    for (int i = 0; i < 16; i++) {
        int idx = t + NTHREADS * i;
        int row = idx >> 4, c4 = idx & 15;
        float4 v = ((const float4*)gcb)[idx];
        uint32_t bo = row * 128 + c4 * 8;
        cvt_store_pair(smem + SM_B_HI, smem + SM_B_LO, bo,     v.x, v.y);
        cvt_store_pair(smem + SM_B_HI, smem + SM_B_LO, bo + 4, v.z, v.w);
    }
    // ---- c2[n]: thread t owns row t, sequential fmaf ----
    {
        float s = 0.f;
        const float* r = gcb + t * CQ;
        #pragma unroll 8
        for (int k = 0; k < CQ; k++) s = fmaf(r[k], r[k], s);
        s_c2[t] = s;
    }
    __syncthreads();

    // ---- A fragments (register-resident; mapping verified in R10) ----
    const int m0 = wid * 16;
    const int lg = lane >> 3, li = lane & 7;
    const int arow  = m0 + li + ((lg & 1) ? 8 : 0);
    const int akoff = (lg >= 2) ? 16 : 0;
    uint32_t a_hi[16], a_lo[16];
    #pragma unroll
    for (int ks = 0; ks < 4; ks++) {
        uint32_t bo = arow * 128 + ks * 32 + akoff;
        ldmx4(a_hi + ks * 4, sb + SM_A_HI + SW128(bo));
        ldmx4(a_lo + ks * 4, sb + SM_A_LO + SW128(bo));
    }

    const int brow_off = li + ((lg >= 2) ? 8 : 0);
    const int bkoff    = (lg & 1) ? 16 : 0;
    const int r2 = (lane & 3) * 2;

    // top-2 key chains per output row r (K1 <= K2)
    u64 K1[2] = { ~0ull, ~0ull }, K2[2] = { ~0ull, ~0ull };

    // ---- mainloop over 16 n-pair groups ----
    #pragma unroll 2
    for (int np = 0; np < 16; np++) {
        float acch[8], aclh[8], achl[8];
        #pragma unroll
        for (int i = 0; i < 8; i++) { acch[i] = 0.f; aclh[i] = 0.f; achl[i] = 0.f; }

        #pragma unroll
        for (int ks = 0; ks < 4; ks++) {
            uint32_t bh[4], bl[4];
            uint32_t bo = (np * 16 + brow_off) * 128 + ks * 32 + bkoff;
            ldmx4(bh, sb + SM_B_HI + SW128(bo));
            ldmx4(bl, sb + SM_B_LO + SW128(bo));
            mma_bf16(acch + 0, a_hi + ks * 4, bh[0], bh[1]);   // hi*hi
            mma_bf16(acch + 4, a_hi + ks * 4, bh[2], bh[3]);
            mma_bf16(aclh + 0, a_lo + ks * 4, bh[0], bh[1]);   // lo*hi
            mma_bf16(aclh + 4, a_lo + ks * 4, bh[2], bh[3]);
            mma_bf16(achl + 0, a_hi + ks * 4, bl[0], bl[1]);   // hi*lo
            mma_bf16(achl + 4, a_hi + ks * 4, bl[2], bl[3]);
        }

        // ---- branchless top-2 key tournament (ALU pipe, no predicates) ----
        const int nb = np * 16;
        float c2a = s_c2[nb + r2],     c2b = s_c2[nb + r2 + 1];
        float c2c = s_c2[nb + 8 + r2], c2d = s_c2[nb + 8 + r2 + 1];
        #pragma unroll
        for (int r = 0; r < 2; r++) {
            float d0 = fmaf(-2.f, acch[2*r+0] + (aclh[2*r+0] + achl[2*r+0]), c2a);
            float d1 = fmaf(-2.f, acch[2*r+1] + (aclh[2*r+1] + achl[2*r+1]), c2b);
            float d2 = fmaf(-2.f, acch[2*r+4] + (aclh[2*r+4] + achl[2*r+4]), c2c);
            float d3 = fmaf(-2.f, acch[2*r+5] + (aclh[2*r+5] + achl[2*r+5]), c2d);
            u64 k0 = ((u64)ford(d0) << 32) | (uint32_t)(nb + r2);
            u64 k1 = ((u64)ford(d1) << 32) | (uint32_t)(nb + r2 + 1);
            u64 k2 = ((u64)ford(d2) << 32) | (uint32_t)(nb + 8 + r2);
            u64 k3 = ((u64)ford(d3) << 32) | (uint32_t)(nb + 8 + r2 + 1);
            u64 s1 = umin64(k0, k1), s2 = umax64(k0, k1);
            u64 s3 = umin64(k2, k3), s4 = umax64(k2, k3);
            u64 m1 = umin64(s1, s3);
            u64 m2 = umin64(umax64(s1, s3), umin64(s2, s4));
            u64 tt = umax64(K1[r], m1);
            K1[r] = umin64(K1[r], m1);
            K2[r] = umin64(umin64(K2[r], m2), tt);
        }
    }

    // ---- per-row quad top-2 reduce + gap test + exact refine ----
    const unsigned quadmask = 0xFu << (lane & ~3u);
    #pragma unroll
    for (int r = 0; r < 2; r++) {
        const int qrow = m0 + (lane >> 2) + 8 * r;
        u64 k1 = K1[r], k2 = K2[r];
        #pragma unroll
        for (int off = 1; off <= 2; off <<= 1) {
            u64 o1 = __shfl_xor_sync(0xffffffff, k1, off);
            u64 o2 = __shfl_xor_sync(0xffffffff, k2, off);
            u64 tt = umax64(k1, o1);
            k1 = umin64(k1, o1);
            k2 = umin64(umin64(k2, o2), tt);
        }
        // k1 = approx-min key (lowest-n on exact tie), k2 = approx 2nd
        int winner = (int)(k1 & 0xFFu);
        float g1 = iord((uint32_t)(k1 >> 32));
        float g2 = iord((uint32_t)(k2 >> 32));

        if (g2 - g1 < TAU) {
            // exact fp32 scan: quad covers all 256 n (each lane its 64)
            const float* xr = x + ((size_t)(qbase + qrow) * MQ + m) * CQ;
            u64 ek = ~0ull;
            for (int np = 0; np < 16; np++) {
                int nn[4] = { np*16 + r2, np*16 + r2 + 1,
                              np*16 + 8 + r2, np*16 + 8 + r2 + 1 };
                #pragma unroll
                for (int j = 0; j < 4; j++) {
                    float d = exact_dist(xr, gcb + nn[j] * CQ, s_c2[nn[j]]);
                    u64 k = ((u64)ford(d) << 32) | (uint32_t)nn[j];
                    ek = umin64(ek, k);
                }
            }
            #pragma unroll
            for (int off = 1; off <= 2; off <<= 1) {
                u64 ok = __shfl_xor_sync(quadmask, ek, off);
                ek = umin64(ek, ok);
            }
            winner = (int)(ek & 0xFFu);
        }
        if ((lane & 3) == 0) s_win[qrow] = winner;
    }
    __syncwarp();   // each warp reads only the s_win rows it wrote

    // ---- output: warp copies its 16 query rows ----
    #pragma unroll
    for (int i = 0; i < 16; i++) {
        int q = wid * 16 + i;
        int n = s_win[q];
        size_t orow = ((size_t)(qbase + q) * MQ + m) * CQ;
        const float2* src = (const float2*)(gcb + (size_t)n * CQ);
        ((float2*)(out_codes + orow))[lane] = src[lane];
        if (lane == 0 && out_idx)
            out_idx[(size_t)(qbase + q) * MQ + m] = (float)n;
    }
}

extern "C" void kernel_launch(void* const* d_in, const int* in_sizes, int n_in,
                              void* d_out, int out_size) {
    const float* x  = (const float*)d_in[0];
    const float* cb = (const float*)d_in[1];
    if (n_in >= 2 && in_sizes[0] == MQ * NQ * CQ) {
        const float* tmp = x; x = cb; cb = tmp;
    }

    float* out_codes = (float*)d_out;
    float* out_idx   = nullptr;
    const long long codes_elems = (long long)BQ * MQ * CQ;   // 8388608
    if ((long long)out_size >= codes_elems + (long long)BQ * MQ)
        out_idx = out_codes + codes_elems;

    cudaFuncSetAttribute(fq_mma_kernel, cudaFuncAttributeMaxDynamicSharedMemorySize,
                         SM_TOTAL);
    dim3 grid(BQ / QT, MQ);   // 64 x 16 = 1024 CTAs
    fq_mma_kernel<<<grid, NTHREADS, SM_TOTAL>>>(x, cb, out_codes, out_idx);
}

// round 15
// speedup vs baseline: 1.0969x; 1.0969x over previous
#include <cuda_runtime.h>
#include <cuda_bf16.h>
#include <cstdint>

// FactoredQuantizer: B=8192, M=16, N=256, C=64
// R14: mma.sync bf16 3-term split (math verified rel_err=0 since R10), with B
// operands pre-converted into fragment-ordered __device__ scratch by a prep
// kernel and loaded via coalesced L2-hot LDG.128. Smem drops to 34KB/CTA so
// 2 CTAs/SM co-reside (the 97KB footprint was capping R10-R13 at 1 CTA/SM).

#define BQ 8192
#define MQ 16
#define NQ 256
#define CQ 64
#define QT 128
#define NTHREADS 256
#define TAU 0.015625f

#define SW128(bo) ((bo) ^ (((bo) >> 3) & 0x70))

// smem: A hi/lo tiles (SW128) + c2 + winners
#define SM_A_HI 0            // [128][64] bf16 = 16 KB
#define SM_A_LO 16384
#define SM_C2   32768        // 256 f32
#define SM_WIN  33792        // 128 int
#define SM_TOTAL 34304

typedef unsigned long long u64;

// B fragments: [m][np][ks][lane] -> uint4 (regs bh[0..3]); 16*16*4*32 = 65536
__device__ uint4 g_bhi[65536];
__device__ uint4 g_blo[65536];

__device__ __forceinline__ uint32_t smem_u32(const void* p) {
    uint32_t a;
    asm("{ .reg .u64 t; cvta.to.shared.u64 t, %1; cvt.u32.u64 %0, t; }"
        : "=r"(a) : "l"(p));
    return a;
}
__device__ __forceinline__ void ldmx4(uint32_t* r, uint32_t addr) {
    asm volatile("ldmatrix.sync.aligned.m8n8.x4.shared.b16 {%0,%1,%2,%3}, [%4];"
                 : "=r"(r[0]), "=r"(r[1]), "=r"(r[2]), "=r"(r[3]) : "r"(addr));
}
__device__ __forceinline__ void mma_bf16(float* c, const uint32_t* a,
                                         uint32_t b0, uint32_t b1) {
    asm volatile(
        "mma.sync.aligned.m16n8k16.row.col.f32.bf16.bf16.f32 "
        "{%0,%1,%2,%3}, {%4,%5,%6,%7}, {%8,%9}, {%0,%1,%2,%3};"
        : "+f"(c[0]), "+f"(c[1]), "+f"(c[2]), "+f"(c[3])
        : "r"(a[0]), "r"(a[1]), "r"(a[2]), "r"(a[3]), "r"(b0), "r"(b1));
}
__device__ __forceinline__ uint32_t ford(float f) {
    uint32_t u = __float_as_uint(f);
    return u ^ ((uint32_t)((int)u >> 31) | 0x80000000u);
}
__device__ __forceinline__ float iord(uint32_t o) {
    uint32_t u = (o & 0x80000000u) ? (o ^ 0x80000000u) : ~o;
    return __uint_as_float(u);
}
__device__ __forceinline__ u64 umin64(u64 a, u64 b) { return a < b ? a : b; }
__device__ __forceinline__ u64 umax64(u64 a, u64 b) { return a < b ? b : a; }

__device__ __forceinline__ uint32_t pack_hi(float a, float b) {
    return (uint32_t)__bfloat16_as_ushort(__float2bfloat16(a))
         | ((uint32_t)__bfloat16_as_ushort(__float2bfloat16(b)) << 16);
}
__device__ __forceinline__ uint32_t pack_lo(float a, float b) {
    float la = a - __bfloat162float(__float2bfloat16(a));
    float lb = b - __bfloat162float(__float2bfloat16(b));
    return (uint32_t)__bfloat16_as_ushort(__float2bfloat16(la))
         | ((uint32_t)__bfloat16_as_ushort(__float2bfloat16(lb)) << 16);
}

__device__ __forceinline__ void cvt_store_pair(char* hi_base, char* lo_base,
                                               uint32_t bo, float a, float b) {
    uint32_t so = SW128(bo);
    *(uint32_t*)(hi_base + so) = pack_hi(a, b);
    *(uint32_t*)(lo_base + so) = pack_lo(a, b);
}

__device__ __forceinline__ float exact_dist(const float* __restrict__ xr,
                                            const float* __restrict__ cr,
                                            float c2n) {
    float s = 0.f;
    #pragma unroll 8
    for (int k = 0; k < CQ; k++) s = fmaf(xr[k], cr[k], s);
    return fmaf(-2.0f, s, c2n);
}

// ---- prep: codebook f32 -> bf16 hi/lo in mma fragment order ----
// Mapping derived from verified R13 ldmatrix use:
//   reg j of lane l covers n = np*16 + l/4 + (j>=2 ? 8 : 0),
//                          k = ks*16 + (l%4)*2 + (j&1 ? 8 : 0), 2 elems (k,k+1)
__global__ void fq_prep_kernel(const float* __restrict__ cb) {
    int idx = blockIdx.x * blockDim.x + threadIdx.x;   // 0..65535
    int lane = idx & 31;
    int ks = (idx >> 5) & 3;
    int np = (idx >> 7) & 15;
    int m  = idx >> 11;
    const float* gcb = cb + (size_t)m * NQ * CQ;
    uint32_t hi[4], lo[4];
    #pragma unroll
    for (int j = 0; j < 4; j++) {
        int n  = np * 16 + (lane >> 2) + ((j & 2) ? 8 : 0);
        int k0 = ks * 16 + (lane & 3) * 2 + ((j & 1) ? 8 : 0);
        float a = gcb[n * CQ + k0], b = gcb[n * CQ + k0 + 1];
        hi[j] = pack_hi(a, b);
        lo[j] = pack_lo(a, b);
    }
    g_bhi[idx] = make_uint4(hi[0], hi[1], hi[2], hi[3]);
    g_blo[idx] = make_uint4(lo[0], lo[1], lo[2], lo[3]);
}

__global__ __launch_bounds__(NTHREADS, 2)
void fq_mma_kernel(const float* __restrict__ x,
                   const float* __restrict__ cb,
                   float* __restrict__ out_codes,
                   float* __restrict__ out_idx) {
    extern __shared__ char smem[];
    const uint32_t sb = smem_u32(smem);
    float* s_c2  = (float*)(smem + SM_C2);
    int*   s_win = (int*)  (smem + SM_WIN);

    const int t = threadIdx.x, wid = t >> 5, lane = t & 31;
    const int m = blockIdx.y;
    const int qbase = blockIdx.x * QT;
    const float* gcb = cb + (size_t)m * NQ * CQ;

    // ---- stage A = x tile [128][64]: f32 -> bf16 hi/lo, SW128 ----
    #pragma unroll
    for (int i = 0; i < 8; i++) {
        int idx = t + NTHREADS * i;
        int row = idx >> 4, c4 = idx & 15;
        float4 v = *(const float4*)(x + ((size_t)(qbase + row) * MQ + m) * CQ + c4 * 4);
        uint32_t bo = row * 128 + c4 * 8;
        cvt_store_pair(smem + SM_A_HI, smem + SM_A_LO, bo,     v.x, v.y);
        cvt_store_pair(smem + SM_A_HI, smem + SM_A_LO, bo + 4, v.z, v.w);
    }
    // ---- c2[n]: thread t owns row t, sequential fmaf ----
    {
        float s = 0.f;
        const float* r = gcb + t * CQ;
        #pragma unroll 8
        for (int k = 0; k < CQ; k++) s = fmaf(r[k], r[k], s);
        s_c2[t] = s;
    }
    __syncthreads();

    // ---- A fragments (register-resident; mapping verified in R10) ----
    const int m0 = wid * 16;
    const int lg = lane >> 3, li = lane & 7;
    const int arow  = m0 + li + ((lg & 1) ? 8 : 0);
    const int akoff = (lg >= 2) ? 16 : 0;
    uint32_t a_hi[16], a_lo[16];
    #pragma unroll
    for (int ks = 0; ks < 4; ks++) {
        uint32_t bo = arow * 128 + ks * 32 + akoff;
        ldmx4(a_hi + ks * 4, sb + SM_A_HI + SW128(bo));
        ldmx4(a_lo + ks * 4, sb + SM_A_LO + SW128(bo));
    }

    const int r2 = (lane & 3) * 2;
    const uint4* fhi = g_bhi + ((size_t)m * 16) * 4 * 32 + lane;
    const uint4* flo = g_blo + ((size_t)m * 16) * 4 * 32 + lane;

    u64 K1[2] = { ~0ull, ~0ull }, K2[2] = { ~0ull, ~0ull };

    // ---- mainloop over 16 n-pair groups; B frags via L2-hot LDG.128 ----
    #pragma unroll 2
    for (int np = 0; np < 16; np++) {
        float acch[8], aclh[8], achl[8];
        #pragma unroll
        for (int i = 0; i < 8; i++) { acch[i] = 0.f; aclh[i] = 0.f; achl[i] = 0.f; }

        #pragma unroll
        for (int ks = 0; ks < 4; ks++) {
            uint4 bh4 = fhi[(np * 4 + ks) * 32];
            uint4 bl4 = flo[(np * 4 + ks) * 32];
            mma_bf16(acch + 0, a_hi + ks * 4, bh4.x, bh4.y);   // hi*hi
            mma_bf16(acch + 4, a_hi + ks * 4, bh4.z, bh4.w);
            mma_bf16(aclh + 0, a_lo + ks * 4, bh4.x, bh4.y);   // lo*hi
            mma_bf16(aclh + 4, a_lo + ks * 4, bh4.z, bh4.w);
            mma_bf16(achl + 0, a_hi + ks * 4, bl4.x, bl4.y);   // hi*lo
            mma_bf16(achl + 4, a_hi + ks * 4, bl4.z, bl4.w);
        }

        const int nb = np * 16;
        float c2a = s_c2[nb + r2],     c2b = s_c2[nb + r2 + 1];
        float c2c = s_c2[nb + 8 + r2], c2d = s_c2[nb + 8 + r2 + 1];
        #pragma unroll
        for (int r = 0; r < 2; r++) {
            float d0 = fmaf(-2.f, acch[2*r+0] + (aclh[2*r+0] + achl[2*r+0]), c2a);
            float d1 = fmaf(-2.f, acch[2*r+1] + (aclh[2*r+1] + achl[2*r+1]), c2b);
            float d2 = fmaf(-2.f, acch[2*r+4] + (aclh[2*r+4] + achl[2*r+4]), c2c);
            float d3 = fmaf(-2.f, acch[2*r+5] + (aclh[2*r+5] + achl[2*r+5]), c2d);
            u64 k0 = ((u64)ford(d0) << 32) | (uint32_t)(nb + r2);
            u64 k1 = ((u64)ford(d1) << 32) | (uint32_t)(nb + r2 + 1);
            u64 k2 = ((u64)ford(d2) << 32) | (uint32_t)(nb + 8 + r2);
            u64 k3 = ((u64)ford(d3) << 32) | (uint32_t)(nb + 8 + r2 + 1);
            u64 s1 = umin64(k0, k1), s2 = umax64(k0, k1);
            u64 s3 = umin64(k2, k3), s4 = umax64(k2, k3);
            u64 m1 = umin64(s1, s3);
            u64 m2 = umin64(umax64(s1, s3), umin64(s2, s4));
            u64 tt = umax64(K1[r], m1);
            K1[r] = umin64(K1[r], m1);
            K2[r] = umin64(umin64(K2[r], m2), tt);
        }
    }

    // ---- per-row quad top-2 reduce + gap test + exact refine ----
    const unsigned quadmask = 0xFu << (lane & ~3u);
    #pragma unroll
    for (int r = 0; r < 2; r++) {
        const int qrow = m0 + (lane >> 2) + 8 * r;
        u64 k1 = K1[r], k2 = K2[r];
        #pragma unroll
        for (int off = 1; off <= 2; off <<= 1) {
            u64 o1 = __shfl_xor_sync(0xffffffff, k1, off);
            u64 o2 = __shfl_xor_sync(0xffffffff, k2, off);
            u64 tt = umax64(k1, o1);
            k1 = umin64(k1, o1);
            k2 = umin64(umin64(k2, o2), tt);
        }
        int winner = (int)(k1 & 0xFFu);
        float g1 = iord((uint32_t)(k1 >> 32));
        float g2 = iord((uint32_t)(k2 >> 32));

        if (g2 - g1 < TAU) {
            // exact fp32 scan: quad covers all 256 n (each lane its 64)
            const float* xr = x + ((size_t)(qbase + qrow) * MQ + m) * CQ;
            u64 ek = ~0ull;
            for (int np = 0; np < 16; np++) {
                int nn[4] = { np*16 + r2, np*16 + r2 + 1,
                              np*16 + 8 + r2, np*16 + 8 + r2 + 1 };
                #pragma unroll
                for (int j = 0; j < 4; j++) {
                    float d = exact_dist(xr, gcb + nn[j] * CQ, s_c2[nn[j]]);
                    u64 k = ((u64)ford(d) << 32) | (uint32_t)nn[j];
                    ek = umin64(ek, k);
                }
            }
            #pragma unroll
            for (int off = 1; off <= 2; off <<= 1) {
                u64 ok = __shfl_xor_sync(quadmask, ek, off);
                ek = umin64(ek, ok);
            }
            winner = (int)(ek & 0xFFu);
        }
        if ((lane & 3) == 0) s_win[qrow] = winner;
    }
    __syncwarp();   // each warp reads only the s_win rows it wrote

    // ---- output: warp copies its 16 query rows ----
    #pragma unroll
    for (int i = 0; i < 16; i++) {
        int q = wid * 16 + i;
        int n = s_win[q];
        size_t orow = ((size_t)(qbase + q) * MQ + m) * CQ;
        const float2* src = (const float2*)(gcb + (size_t)n * CQ);
        ((float2*)(out_codes + orow))[lane] = src[lane];
        if (lane == 0 && out_idx)
            out_idx[(size_t)(qbase + q) * MQ + m] = (float)n;
    }
}

extern "C" void kernel_launch(void* const* d_in, const int* in_sizes, int n_in,
                              void* d_out, int out_size) {
    const float* x  = (const float*)d_in[0];
    const float* cb = (const float*)d_in[1];
    if (n_in >= 2 && in_sizes[0] == MQ * NQ * CQ) {
        const float* tmp = x; x = cb; cb = tmp;
    }

    float* out_codes = (float*)d_out;
    float* out_idx   = nullptr;
    const long long codes_elems = (long long)BQ * MQ * CQ;   // 8388608
    if ((long long)out_size >= codes_elems + (long long)BQ * MQ)
        out_idx = out_codes + codes_elems;

    // prep: codebook -> fragment-ordered bf16 hi/lo scratch (same stream)
    fq_prep_kernel<<<256, 256>>>(cb);

    cudaFuncSetAttribute(fq_mma_kernel, cudaFuncAttributeMaxDynamicSharedMemorySize,
                         SM_TOTAL);
    dim3 grid(BQ / QT, MQ);   // 64 x 16 = 1024 CTAs
    fq_mma_kernel<<<grid, NTHREADS, SM_TOTAL>>>(x, cb, out_codes, out_idx);
}

// round 16
// speedup vs baseline: 2.5524x; 2.3270x over previous
#include <cuda_runtime.h>
#include <cuda_bf16.h>
#include <cstdint>

// FactoredQuantizer: B=8192, M=16, N=256, C=64
// R15: scalar FFMA2 outer product rebalanced: 16 queries/warp x 2 codes/lane
// per pass (4 passes). Crossbar cost per FMA drops ~2x vs R9; fma pipe is the
// sole limiter. u64-key argmin (exact fp32 dists, first-index tie-break).
// Register budget kept <=126 so 2 CTAs/SM co-reside (REGCOUNT gap: 128 regs
// declared = 130 consumed = 1 CTA, the hidden killer of R10-R14).

#define BQ 8192
#define MQ 16
#define NQ 256
#define CQ 64
#define QW 16             // queries per warp
#define NTHREADS 256      // 8 warps -> 128 queries per block
#define QB 128
#define CPAD 68           // padded code row (272 B): conflict-free distinct LDS

typedef unsigned long long u64;

__device__ __forceinline__ u64 ffma2(u64 a, u64 b, u64 c) {
    u64 d;
    asm("fma.rn.f32x2 %0, %1, %2, %3;" : "=l"(d) : "l"(a), "l"(b), "l"(c));
    return d;
}
__device__ __forceinline__ float sum2(u64 s) {
    float lo = __uint_as_float((unsigned)s);
    float hi = __uint_as_float((unsigned)(s >> 32));
    return lo + hi;
}
// monotone float -> ordered u32 (ascending)
__device__ __forceinline__ uint32_t ford(float f) {
    uint32_t u = __float_as_uint(f);
    return u ^ ((uint32_t)((int)u >> 31) | 0x80000000u);
}
__device__ __forceinline__ u64 umin64(u64 a, u64 b) { return a < b ? a : b; }

// smem: codebook padded [256][68] f32 | x [128][64] f32 | c2 [256] f32
#define SM_CB_BYTES (NQ * CPAD * 4)            // 69632
#define SM_X_OFF    SM_CB_BYTES
#define SM_X_BYTES  (QB * CQ * 4)              // 32768
#define SM_C2_OFF   (SM_X_OFF + SM_X_BYTES)
#define SM_TOTAL    (SM_C2_OFF + NQ * 4)       // 103424

__global__ __launch_bounds__(NTHREADS, 2)
void fq_kernel(const float* __restrict__ x,
               const float* __restrict__ cb,
               float* __restrict__ out_codes,
               float* __restrict__ out_idx) {
    extern __shared__ char smem[];
    float* s_cb = (float*)smem;                 // padded rows
    float* s_x  = (float*)(smem + SM_X_OFF);
    float* s_c2 = (float*)(smem + SM_C2_OFF);

    const int t    = threadIdx.x;
    const int wid  = t >> 5;
    const int lane = t & 31;
    const int m     = blockIdx.y;
    const int qbase = blockIdx.x * QB;

    // ---- stage codebook[m] into padded rows (gmem reads L2-hot) ----
    {
        const float4* g = (const float4*)(cb + (size_t)m * NQ * CQ);
        #pragma unroll
        for (int i = 0; i < 16; i++) {
            int idx = t + NTHREADS * i;         // 0..4095
            int n = idx >> 4, k4 = idx & 15;
            float4 v = g[idx];
            *(float4*)(s_cb + n * CPAD + k4 * 4) = v;
        }
    }
    // ---- stage x tile [128][64] ----
    {
        #pragma unroll
        for (int i = 0; i < 8; i++) {
            int idx = t + NTHREADS * i;         // 0..2047
            int q = idx >> 4, k4 = idx & 15;
            float4 v = *(const float4*)(x + ((size_t)(qbase + q) * MQ + m) * CQ + k4 * 4);
            *(float4*)(s_x + q * CQ + k4 * 4) = v;
        }
    }
    __syncthreads();

    // ---- c2[n] (thread t owns row n=t; sequential fmaf) ----
    {
        float s = 0.f;
        const float* row = s_cb + t * CPAD;
        #pragma unroll
        for (int k = 0; k < CQ; k++) s = fmaf(row[k], row[k], s);
        s_c2[t] = s;
    }
    __syncthreads();

    // ---- main: warp wid owns 16 queries; lanes split codes (2/pass) ----
    const float* xw = s_x + (wid * QW) * CQ;
    u64 K[QW];
    #pragma unroll
    for (int q = 0; q < QW; q++) K[q] = ~0ull;

    #pragma unroll 1
    for (int p = 0; p < 4; p++) {
        const int n0 = lane + 64 * p;           // lane's rows: n0, n0+32
        const char* c0 = (const char*)(s_cb + n0 * CPAD);
        const char* c1 = (const char*)(s_cb + (n0 + 32) * CPAD);

        u64 acc0[QW], acc1[QW];
        #pragma unroll
        for (int q = 0; q < QW; q++) { acc0[q] = 0ull; acc1[q] = 0ull; }

        #pragma unroll 4
        for (int ch = 0; ch < 16; ch++) {       // 4 k-floats per chunk
            ulonglong2 cv0 = *(const ulonglong2*)(c0 + ch * 16);  // distinct
            ulonglong2 cv1 = *(const ulonglong2*)(c1 + ch * 16);  // distinct
            #pragma unroll
            for (int q = 0; q < QW; q++) {
                ulonglong2 xv = *(const ulonglong2*)(xw + q * CQ + ch * 4); // bcast
                acc0[q] = ffma2(xv.x, cv0.x, acc0[q]);
                acc0[q] = ffma2(xv.y, cv0.y, acc0[q]);
                acc1[q] = ffma2(xv.x, cv1.x, acc1[q]);
                acc1[q] = ffma2(xv.y, cv1.y, acc1[q]);
            }
        }

        // dist = c2[n] - 2*dot ; u64 key keeps first-index tie-break
        const float c20 = s_c2[n0];
        const float c21 = s_c2[n0 + 32];
        #pragma unroll
        for (int q = 0; q < QW; q++) {
            float d0 = fmaf(-2.0f, sum2(acc0[q]), c20);
            float d1 = fmaf(-2.0f, sum2(acc1[q]), c21);
            u64 k0 = ((u64)ford(d0) << 32) | (uint32_t)n0;
            u64 k1 = ((u64)ford(d1) << 32) | (uint32_t)(n0 + 32);
            K[q] = umin64(K[q], umin64(k0, k1));
        }
    }

    // ---- cross-lane key-min per query (ties -> lower n automatically) ----
    #pragma unroll
    for (int q = 0; q < QW; q++) {
        u64 k = K[q];
        #pragma unroll
        for (int o = 16; o > 0; o >>= 1)
            k = umin64(k, __shfl_xor_sync(0xffffffff, k, o));
        K[q] = k;
    }

    // ---- output: warp copies its 16 winning rows (gmem codebook L2-hot) ----
    #pragma unroll
    for (int q = 0; q < QW; q++) {
        int n = (int)(K[q] & 0xFFu);
        int qq = wid * QW + q;
        size_t orow = ((size_t)(qbase + qq) * MQ + m) * CQ;
        const float2* src = (const float2*)(cb + ((size_t)m * NQ + n) * CQ);
        ((float2*)(out_codes + orow))[lane] = src[lane];
        if (lane == 0 && out_idx)
            out_idx[(size_t)(qbase + qq) * MQ + m] = (float)n;
    }
}

extern "C" void kernel_launch(void* const* d_in, const int* in_sizes, int n_in,
                              void* d_out, int out_size) {
    const float* x  = (const float*)d_in[0];
    const float* cb = (const float*)d_in[1];
    if (n_in >= 2 && in_sizes[0] == MQ * NQ * CQ) {
        const float* tmp = x; x = cb; cb = tmp;
    }

    float* out_codes = (float*)d_out;
    float* out_idx   = nullptr;
    const long long codes_elems = (long long)BQ * MQ * CQ;   // 8388608
    if ((long long)out_size >= codes_elems + (long long)BQ * MQ)
        out_idx = out_codes + codes_elems;

    cudaFuncSetAttribute(fq_kernel, cudaFuncAttributeMaxDynamicSharedMemorySize,
                         SM_TOTAL);
    dim3 grid(BQ / QB, MQ);   // 64 x 16 = 1024 CTAs
    fq_kernel<<<grid, NTHREADS, SM_TOTAL>>>(x, cb, out_codes, out_idx);
}

// round 17
// speedup vs baseline: 2.8119x; 1.1017x over previous
#include <cuda_runtime.h>
#include <cuda_bf16.h>
#include <cstdint>

// FactoredQuantizer: B=8192, M=16, N=256, C=64
// R16: scalar FFMA2 outer product, crossbar/fma co-balanced tiling:
// 8 queries/warp x 4 codes/lane (2 passes). Per 4k-chunk: 32 crossbar-wf
// (16 bcast + 16 distinct) vs 128 SMSP-cyc fma -> both pipes ~equal (R15's
// broadcast-heavy 40wf made the crossbar the binder). Exact fp32 math,
// u64-key argmin (first-index ties), 2 CTAs/SM.

#define BQ 8192
#define MQ 16
#define NQ 256
#define CQ 64
#define QW 8              // queries per warp
#define NC 4              // codes per lane per pass
#define NTHREADS 256      // 8 warps -> 64 queries per block
#define QB 64
#define CPAD 68           // padded code row (272 B): conflict-free distinct LDS

typedef unsigned long long u64;

__device__ __forceinline__ u64 ffma2(u64 a, u64 b, u64 c) {
    u64 d;
    asm("fma.rn.f32x2 %0, %1, %2, %3;" : "=l"(d) : "l"(a), "l"(b), "l"(c));
    return d;
}
__device__ __forceinline__ float sum2(u64 s) {
    float lo = __uint_as_float((unsigned)s);
    float hi = __uint_as_float((unsigned)(s >> 32));
    return lo + hi;
}
__device__ __forceinline__ uint32_t ford(float f) {
    uint32_t u = __float_as_uint(f);
    return u ^ ((uint32_t)((int)u >> 31) | 0x80000000u);
}
__device__ __forceinline__ u64 umin64(u64 a, u64 b) { return a < b ? a : b; }

// smem: codebook padded [256][68] f32 | x [64][64] f32 | c2 [256] f32
#define SM_CB_BYTES (NQ * CPAD * 4)            // 69632
#define SM_X_OFF    SM_CB_BYTES
#define SM_X_BYTES  (QB * CQ * 4)              // 16384
#define SM_C2_OFF   (SM_X_OFF + SM_X_BYTES)
#define SM_TOTAL    (SM_C2_OFF + NQ * 4)       // 87040

__global__ __launch_bounds__(NTHREADS, 2)
void fq_kernel(const float* __restrict__ x,
               const float* __restrict__ cb,
               float* __restrict__ out_codes,
               float* __restrict__ out_idx) {
    extern __shared__ char smem[];
    float* s_cb = (float*)smem;                 // padded rows
    float* s_x  = (float*)(smem + SM_X_OFF);
    float* s_c2 = (float*)(smem + SM_C2_OFF);

    const int t    = threadIdx.x;
    const int wid  = t >> 5;
    const int lane = t & 31;
    const int m     = blockIdx.y;
    const int qbase = blockIdx.x * QB;

    // ---- stage codebook[m] into padded rows ----
    {
        const float4* g = (const float4*)(cb + (size_t)m * NQ * CQ);
        #pragma unroll
        for (int i = 0; i < 16; i++) {
            int idx = t + NTHREADS * i;         // 0..4095
            int n = idx >> 4, k4 = idx & 15;
            float4 v = g[idx];
            *(float4*)(s_cb + n * CPAD + k4 * 4) = v;
        }
    }
    // ---- stage x tile [64][64] ----
    {
        #pragma unroll
        for (int i = 0; i < 4; i++) {
            int idx = t + NTHREADS * i;         // 0..1023
            int q = idx >> 4, k4 = idx & 15;
            float4 v = *(const float4*)(x + ((size_t)(qbase + q) * MQ + m) * CQ + k4 * 4);
            *(float4*)(s_x + q * CQ + k4 * 4) = v;
        }
    }
    __syncthreads();

    // ---- c2[n] (thread t owns row n=t; sequential fmaf) ----
    {
        float s = 0.f;
        const float* row = s_cb + t * CPAD;
        #pragma unroll
        for (int k = 0; k < CQ; k++) s = fmaf(row[k], row[k], s);
        s_c2[t] = s;
    }
    __syncthreads();

    // ---- main: warp wid owns 8 queries; lane owns 4 codes per pass ----
    const float* xw = s_x + (wid * QW) * CQ;
    u64 K[QW];
    #pragma unroll
    for (int q = 0; q < QW; q++) K[q] = ~0ull;

    #pragma unroll 1
    for (int p = 0; p < 2; p++) {
        // lane's code rows: n = lane + 32j + 128p, j = 0..3
        const char* cr[NC];
        #pragma unroll
        for (int j = 0; j < NC; j++)
            cr[j] = (const char*)(s_cb + (lane + 32 * j + 128 * p) * CPAD);

        u64 acc[QW][NC];
        #pragma unroll
        for (int q = 0; q < QW; q++)
            #pragma unroll
            for (int j = 0; j < NC; j++) acc[q][j] = 0ull;

        #pragma unroll 4
        for (int ch = 0; ch < 16; ch++) {       // 4 k-floats per chunk
            ulonglong2 cv[NC];
            #pragma unroll
            for (int j = 0; j < NC; j++)
                cv[j] = *(const ulonglong2*)(cr[j] + ch * 16);   // distinct rows
            #pragma unroll
            for (int q = 0; q < QW; q++) {
                ulonglong2 xv = *(const ulonglong2*)(xw + q * CQ + ch * 4); // bcast
                #pragma unroll
                for (int j = 0; j < NC; j++) {
                    acc[q][j] = ffma2(xv.x, cv[j].x, acc[q][j]);
                    acc[q][j] = ffma2(xv.y, cv[j].y, acc[q][j]);
                }
            }
        }

        // dist = c2[n] - 2*dot ; u64 key keeps first-index tie-break
        #pragma unroll
        for (int j = 0; j < NC; j++) {
            const int n = lane + 32 * j + 128 * p;
            const float c2n = s_c2[n];
            #pragma unroll
            for (int q = 0; q < QW; q++) {
                float d = fmaf(-2.0f, sum2(acc[q][j]), c2n);
                u64 k = ((u64)ford(d) << 32) | (uint32_t)n;
                K[q] = umin64(K[q], k);
            }
        }
    }

    // ---- cross-lane key-min per query (ties -> lower n automatically) ----
    #pragma unroll
    for (int q = 0; q < QW; q++) {
        u64 k = K[q];
        #pragma unroll
        for (int o = 16; o > 0; o >>= 1)
            k = umin64(k, __shfl_xor_sync(0xffffffff, k, o));
        K[q] = k;
    }

    // ---- output: warp copies its 8 winning rows (gmem codebook L2-hot) ----
    #pragma unroll
    for (int q = 0; q < QW; q++) {
        int n = (int)(K[q] & 0xFFu);
        int qq = wid * QW + q;
        size_t orow = ((size_t)(qbase + qq) * MQ + m) * CQ;
        const float2* src = (const float2*)(cb + ((size_t)m * NQ + n) * CQ);
        ((float2*)(out_codes + orow))[lane] = src[lane];
        if (lane == 0 && out_idx)
            out_idx[(size_t)(qbase + qq) * MQ + m] = (float)n;
    }
}

extern "C" void kernel_launch(void* const* d_in, const int* in_sizes, int n_in,
                              void* d_out, int out_size) {
    const float* x  = (const float*)d_in[0];
    const float* cb = (const float*)d_in[1];
    if (n_in >= 2 && in_sizes[0] == MQ * NQ * CQ) {
        const float* tmp = x; x = cb; cb = tmp;
    }

    float* out_codes = (float*)d_out;
    float* out_idx   = nullptr;
    const long long codes_elems = (long long)BQ * MQ * CQ;   // 8388608
    if ((long long)out_size >= codes_elems + (long long)BQ * MQ)
        out_idx = out_codes + codes_elems;

    cudaFuncSetAttribute(fq_kernel, cudaFuncAttributeMaxDynamicSharedMemorySize,
                         SM_TOTAL);
    dim3 grid(BQ / QB, MQ);   // 128 x 16 = 2048 CTAs
    fq_kernel<<<grid, NTHREADS, SM_TOTAL>>>(x, cb, out_codes, out_idx);
}